// round 16
// baseline (speedup 1.0000x reference)
#include <cuda_runtime.h>
#include <math.h>

#define NN 131072

// ---------------- scratch (static device arrays; no allocations) ----------------
__device__ __align__(16) float g_pooled[NN * 64];
__device__ __align__(16) float g_h1[NN * 128];
__device__ __align__(16) float g_cemb[NN * 64];

__device__ __forceinline__ float gelu_f(float x) {
    return 0.5f * x * (1.0f + erff(x * 0.70710678118654752f));
}
__device__ __forceinline__ float to_tf32(float x) {
    unsigned r;
    asm("cvt.rna.tf32.f32 %0, %1;" : "=r"(r) : "f"(x));
    return __uint_as_float(r);
}
__device__ __forceinline__ float4 tf32x4(float4 v) {
    v.x = to_tf32(v.x); v.y = to_tf32(v.y); v.z = to_tf32(v.z); v.w = to_tf32(v.w);
    return v;
}
__device__ __forceinline__ void mma8(float* c, const unsigned* a, const unsigned* b) {
    asm("mma.sync.aligned.m16n8k8.row.col.f32.tf32.tf32.f32 "
        "{%0,%1,%2,%3}, {%4,%5,%6,%7}, {%8,%9}, {%0,%1,%2,%3};"
        : "+f"(c[0]), "+f"(c[1]), "+f"(c[2]), "+f"(c[3])
        : "r"(a[0]), "r"(a[1]), "r"(a[2]), "r"(a[3]), "r"(b[0]), "r"(b[1]));
}

extern __shared__ float dsm[];

// ---- 8-warp helpers: row-warp rw=wp&3 (R=rw*16), col-warp cw=wp>>1&..; 4 n-tiles/warp ----
// mma over K=64: A rows R..R+15 (stride-68 smem), W cols cw*32..+31 (stride-68 smem)
__device__ __forceinline__ void mma_stage8(const float* sA, const float* sW,
                                           float acc[4][4], int R, int cw, int g, int t) {
#pragma unroll
    for (int k8 = 0; k8 < 8; k8++) {
        int kb = k8 * 8;
        unsigned a[4], bb[4][2];
        a[0] = __float_as_uint(sA[(R + g) * 68 + kb + t]);
        a[1] = __float_as_uint(sA[(R + g + 8) * 68 + kb + t]);
        a[2] = __float_as_uint(sA[(R + g) * 68 + kb + t + 4]);
        a[3] = __float_as_uint(sA[(R + g + 8) * 68 + kb + t + 4]);
#pragma unroll
        for (int n = 0; n < 4; n++) {
            int cc = cw * 32 + n * 8 + g;
            bb[n][0] = __float_as_uint(sW[cc * 68 + kb + t]);
            bb[n][1] = __float_as_uint(sW[cc * 68 + kb + t + 4]);
        }
#pragma unroll
        for (int n = 0; n < 4; n++) mma8(acc[n], a, bb[n]);
    }
}
__device__ __forceinline__ void scatter8(float* dst, const float acc[4][4],
                                         const float* __restrict__ bias,
                                         int R, int cw, int g, int t) {
#pragma unroll
    for (int n = 0; n < 4; n++) {
        int col = cw * 32 + n * 8 + 2 * t;
        float b0 = __ldg(bias + col);
        float b1 = __ldg(bias + col + 1);
        *(float2*)(dst + (R + g) * 68 + col) = make_float2(acc[n][0] + b0, acc[n][1] + b1);
        *(float2*)(dst + (R + g + 8) * 68 + col) = make_float2(acc[n][2] + b0, acc[n][3] + b1);
    }
}
// full-width (8 n-tile) mma for 16 rows — used by the 128-row inter branch
__device__ __forceinline__ void mma_stage16(const float* sA, const float* sW,
                                            float acc[8][4], int R, int g, int t) {
#pragma unroll
    for (int k8 = 0; k8 < 8; k8++) {
        int kb = k8 * 8;
        unsigned a[4], bb[8][2];
        a[0] = __float_as_uint(sA[(R + g) * 68 + kb + t]);
        a[1] = __float_as_uint(sA[(R + g + 8) * 68 + kb + t]);
        a[2] = __float_as_uint(sA[(R + g) * 68 + kb + t + 4]);
        a[3] = __float_as_uint(sA[(R + g + 8) * 68 + kb + t + 4]);
#pragma unroll
        for (int n = 0; n < 8; n++) {
            bb[n][0] = __float_as_uint(sW[(n * 8 + g) * 68 + kb + t]);
            bb[n][1] = __float_as_uint(sW[(n * 8 + g) * 68 + kb + t + 4]);
        }
#pragma unroll
        for (int n = 0; n < 8; n++) mma8(acc[n], a, bb[n]);
    }
}
// LayerNorm over 64 rows of a stride-68 region; 256 threads, 4 thr/row, tf32 store
__device__ __forceinline__ void ln64_256(float* buf, const float* __restrict__ gamma,
                                         const float* __restrict__ beta, int tid,
                                         int doGelu) {
    int r = tid >> 2, c0 = (tid & 3) * 16;
    float4 cv[4];
#pragma unroll
    for (int q = 0; q < 4; q++) cv[q] = *(float4*)(buf + r * 68 + c0 + q * 4);
    float s1 = 0.0f, s2 = 0.0f;
#pragma unroll
    for (int q = 0; q < 4; q++) {
        s1 += cv[q].x + cv[q].y + cv[q].z + cv[q].w;
        s2 += cv[q].x * cv[q].x + cv[q].y * cv[q].y + cv[q].z * cv[q].z + cv[q].w * cv[q].w;
    }
    s1 += __shfl_xor_sync(0xffffffffu, s1, 1, 4);
    s1 += __shfl_xor_sync(0xffffffffu, s1, 2, 4);
    s2 += __shfl_xor_sync(0xffffffffu, s2, 1, 4);
    s2 += __shfl_xor_sync(0xffffffffu, s2, 2, 4);
    float mean = s1 * (1.0f / 64.0f);
    float var = s2 * (1.0f / 64.0f) - mean * mean;
    float rstd = rsqrtf(var + 1e-5f);
#pragma unroll
    for (int q = 0; q < 4; q++) {
        int c = c0 + q * 4;
        float4 gq = *(const float4*)(gamma + c);
        float4 eq = *(const float4*)(beta + c);
        float4 o;
        o.x = (cv[q].x - mean) * rstd * gq.x + eq.x;
        o.y = (cv[q].y - mean) * rstd * gq.y + eq.y;
        o.z = (cv[q].z - mean) * rstd * gq.z + eq.z;
        o.w = (cv[q].w - mean) * rstd * gq.w + eq.w;
        if (doGelu) { o.x = gelu_f(o.x); o.y = gelu_f(o.y); o.z = gelu_f(o.z); o.w = gelu_f(o.w); }
        o = tf32x4(o);
        *(float4*)(buf + r * 68 + c) = o;
    }
}

// =====================================================================
// k_front: 256 threads, 8 warps. attention (8192) + inter (2048) + ci (2048)
// bx%6==0 -> inter; bx%6==3 -> ci; else attention.
// attention smem: sW 64x68 | sQKV 64x196 (67584 B); others fit inside. 3 CTAs/SM.
// =====================================================================
__global__ void __launch_bounds__(256, 3)
k_front(const float* __restrict__ evx, const float* __restrict__ evy,
        const float* __restrict__ exv, const float* __restrict__ eyv,
        const float* __restrict__ Win, const float* __restrict__ bin,
        const float* __restrict__ Wout, const float* __restrict__ bout,
        const float* __restrict__ g_at, const float* __restrict__ b_at,
        const float* __restrict__ Wi1, const float* __restrict__ bi1,
        const float* __restrict__ cif,
        const float* __restrict__ Wc1, const float* __restrict__ bc1,
        const float* __restrict__ Wc2, const float* __restrict__ bc2,
        const float* __restrict__ gc, const float* __restrict__ bnc)
{
    const int bx = blockIdx.x;
    const int tid = threadIdx.x;
    const int lane = tid & 31, wp = tid >> 5;
    const int g = lane >> 2, t = lane & 3;
    const int r6 = bx % 6, q6 = bx / 6;

    if (r6 != 0 && r6 != 3) {
        // ================= attention branch: 16 nodes (64 rows) =================
        float* sW = dsm;                // 64*68
        float* sQKV = dsm + 64 * 68;    // 64*196
        const int ab = 4 * q6 + (r6 - 1 - (r6 >= 4 ? 1 : 0));
        const int node0 = ab * 16;
        const int rw = wp & 3, cw = wp >> 2;
        const int R = rw * 16;

        // preload A fragments (tf32 edges) from gmem (same for both col-warps)
        float af[8][4];
        {
            int r0 = R + g, r1 = R + g + 8;
            const float* base0 = ((r0 & 3) == 0) ? evx : ((r0 & 3) == 1) ? evy
                               : ((r0 & 3) == 2) ? exv : eyv;
            const float* base1 = ((r1 & 3) == 0) ? evx : ((r1 & 3) == 1) ? evy
                               : ((r1 & 3) == 2) ? exv : eyv;
            const float* p0 = base0 + (size_t)(node0 + (r0 >> 2)) * 64;
            const float* p1 = base1 + (size_t)(node0 + (r1 >> 2)) * 64;
#pragma unroll
            for (int k8 = 0; k8 < 8; k8++) {
                int kb = k8 * 8;
                af[k8][0] = to_tf32(__ldg(p0 + kb + t));
                af[k8][1] = to_tf32(__ldg(p1 + kb + t));
                af[k8][2] = to_tf32(__ldg(p0 + kb + t + 4));
                af[k8][3] = to_tf32(__ldg(p1 + kb + t + 4));
            }
        }

        // QKV: 3 chunks of W_in; each warp does 16 rows x 32 cols
#pragma unroll 1
        for (int wc = 0; wc < 3; wc++) {
            __syncthreads();
            for (int i4 = tid; i4 < 64 * 16; i4 += 256) {
                int c = i4 >> 4, k4 = i4 & 15;
                *(float4*)(sW + c * 68 + k4 * 4) =
                    tf32x4(*(const float4*)(Win + (size_t)(wc * 64 + c) * 64 + k4 * 4));
            }
            __syncthreads();

            float acc[4][4];
#pragma unroll
            for (int n = 0; n < 4; n++)
#pragma unroll
                for (int i = 0; i < 4; i++) acc[n][i] = 0.0f;
#pragma unroll
            for (int k8 = 0; k8 < 8; k8++) {
                int kb = k8 * 8;
                unsigned bb[4][2];
#pragma unroll
                for (int n = 0; n < 4; n++) {
                    int cc = cw * 32 + n * 8 + g;
                    bb[n][0] = __float_as_uint(sW[cc * 68 + kb + t]);
                    bb[n][1] = __float_as_uint(sW[cc * 68 + kb + t + 4]);
                }
                const unsigned* a = (const unsigned*)af[k8];
#pragma unroll
                for (int n = 0; n < 4; n++) mma8(acc[n], a, bb[n]);
            }
            int cb = ((wc < 2) ? wc * 64 : 128) + cw * 32;
#pragma unroll
            for (int n = 0; n < 4; n++) {
                int col = n * 8 + 2 * t;
                float b0 = __ldg(bin + wc * 64 + cw * 32 + col);
                float b1 = __ldg(bin + wc * 64 + cw * 32 + col + 1);
                *(float2*)(sQKV + (R + g) * 196 + cb + col) =
                    make_float2(acc[n][0] + b0, acc[n][1] + b1);
                *(float2*)(sQKV + (R + g + 8) * 196 + cb + col) =
                    make_float2(acc[n][2] + b0, acc[n][3] + b1);
            }
        }
        __syncthreads();

        // attention: 256 threads, thread = (node nl, query qs, head h)
        {
            int nl = tid >> 4, qs = (tid >> 2) & 3, h = tid & 3;
            float* qrow = sQKV + (nl * 4 + qs) * 196;
            float p[4];
#pragma unroll
            for (int ks = 0; ks < 4; ks++) {
                const float* krow = sQKV + (nl * 4 + ks) * 196 + 64;
                float d = 0.0f;
#pragma unroll
                for (int e4 = 0; e4 < 4; e4++) {
                    float4 qv = *(const float4*)(qrow + h * 16 + e4 * 4);
                    float4 kv = *(const float4*)(krow + h * 16 + e4 * 4);
                    d += qv.x * kv.x + qv.y * kv.y + qv.z * kv.z + qv.w * kv.w;
                }
                p[ks] = d * 0.25f;
            }
            float m = fmaxf(fmaxf(p[0], p[1]), fmaxf(p[2], p[3]));
            float s = 0.0f;
#pragma unroll
            for (int ks = 0; ks < 4; ks++) { p[ks] = expf(p[ks] - m); s += p[ks]; }
            float inv = 1.0f / s;
#pragma unroll
            for (int ks = 0; ks < 4; ks++) p[ks] *= inv;
            // ao -> own Q row, cols h*16..h*16+15
#pragma unroll
            for (int e = 0; e < 4; e++) {
                int e4 = h * 4 + e;
                float4 o = {0.0f, 0.0f, 0.0f, 0.0f};
#pragma unroll
                for (int ks = 0; ks < 4; ks++) {
                    float4 v = *(const float4*)(sQKV + (nl * 4 + ks) * 196 + 128 + e4 * 4);
                    float pk = p[ks];
                    o.x += pk * v.x; o.y += pk * v.y; o.z += pk * v.z; o.w += pk * v.w;
                }
                *(float4*)(qrow + e4 * 4) = o;
            }
        }
        __syncthreads();

        // out-proj: stage Wout, mma (16 rows x 32 cols/warp), scatter to cols 64..127
        for (int i4 = tid; i4 < 64 * 16; i4 += 256) {
            int c = i4 >> 4, k4 = i4 & 15;
            *(float4*)(sW + c * 68 + k4 * 4) =
                tf32x4(*(const float4*)(Wout + (size_t)c * 64 + k4 * 4));
        }
        __syncthreads();
        {
            float acc[4][4];
#pragma unroll
            for (int n = 0; n < 4; n++)
#pragma unroll
                for (int i = 0; i < 4; i++) acc[n][i] = 0.0f;
#pragma unroll
            for (int k8 = 0; k8 < 8; k8++) {
                int kb = k8 * 8;
                unsigned a[4], bb[4][2];
                a[0] = __float_as_uint(to_tf32(sQKV[(R + g) * 196 + kb + t]));
                a[1] = __float_as_uint(to_tf32(sQKV[(R + g + 8) * 196 + kb + t]));
                a[2] = __float_as_uint(to_tf32(sQKV[(R + g) * 196 + kb + t + 4]));
                a[3] = __float_as_uint(to_tf32(sQKV[(R + g + 8) * 196 + kb + t + 4]));
#pragma unroll
                for (int n = 0; n < 4; n++) {
                    int cc = cw * 32 + n * 8 + g;
                    bb[n][0] = __float_as_uint(sW[cc * 68 + kb + t]);
                    bb[n][1] = __float_as_uint(sW[cc * 68 + kb + t + 4]);
                }
#pragma unroll
                for (int n = 0; n < 4; n++) mma8(acc[n], a, bb[n]);
            }
#pragma unroll
            for (int n = 0; n < 4; n++) {
                int col = cw * 32 + n * 8 + 2 * t;
                *(float2*)(sQKV + (R + g) * 196 + 64 + col) = make_float2(acc[n][0], acc[n][1]);
                *(float2*)(sQKV + (R + g + 8) * 196 + 64 + col) = make_float2(acc[n][2], acc[n][3]);
            }
        }
        __syncthreads();

        // epilogue: 4 thr/row; +bout +edge residual -> LN -> butterfly pooled mean
        {
            int r = tid >> 2, ch = tid & 3;
            int c0 = ch * 16;
            int node = node0 + (r >> 2), s = r & 3;
            const float* ebase = ((s == 0) ? evx : (s == 1) ? evy : (s == 2) ? exv : eyv)
                                 + (size_t)node * 64;
            float4 cv[4];
#pragma unroll
            for (int q = 0; q < 4; q++) {
                int c = c0 + q * 4;
                float4 v = *(float4*)(sQKV + r * 196 + 64 + c);
                float4 e = *(const float4*)(ebase + c);
                float4 bq = *(const float4*)(bout + c);
                v.x += bq.x + e.x; v.y += bq.y + e.y;
                v.z += bq.z + e.z; v.w += bq.w + e.w;
                cv[q] = v;
            }
            float s1 = 0.0f, s2 = 0.0f;
#pragma unroll
            for (int q = 0; q < 4; q++) {
                s1 += cv[q].x + cv[q].y + cv[q].z + cv[q].w;
                s2 += cv[q].x * cv[q].x + cv[q].y * cv[q].y + cv[q].z * cv[q].z + cv[q].w * cv[q].w;
            }
            s1 += __shfl_xor_sync(0xffffffffu, s1, 1, 4);
            s1 += __shfl_xor_sync(0xffffffffu, s1, 2, 4);
            s2 += __shfl_xor_sync(0xffffffffu, s2, 1, 4);
            s2 += __shfl_xor_sync(0xffffffffu, s2, 2, 4);
            float mean = s1 * (1.0f / 64.0f);
            float var = s2 * (1.0f / 64.0f) - mean * mean;
            float rstd = rsqrtf(var + 1e-5f);
            float4 yv[4];
#pragma unroll
            for (int q = 0; q < 4; q++) {
                int c = c0 + q * 4;
                float4 gq = *(const float4*)(g_at + c);
                float4 eq = *(const float4*)(b_at + c);
                yv[q].x = (cv[q].x - mean) * rstd * gq.x + eq.x;
                yv[q].y = (cv[q].y - mean) * rstd * gq.y + eq.y;
                yv[q].z = (cv[q].z - mean) * rstd * gq.z + eq.z;
                yv[q].w = (cv[q].w - mean) * rstd * gq.w + eq.w;
            }
            // mean over the 4 query slots: threads nl*16 + qs*4 + ch; xor 4, xor 8 (width 16)
#pragma unroll
            for (int q = 0; q < 4; q++) {
                yv[q].x += __shfl_xor_sync(0xffffffffu, yv[q].x, 4, 16);
                yv[q].y += __shfl_xor_sync(0xffffffffu, yv[q].y, 4, 16);
                yv[q].z += __shfl_xor_sync(0xffffffffu, yv[q].z, 4, 16);
                yv[q].w += __shfl_xor_sync(0xffffffffu, yv[q].w, 4, 16);
                yv[q].x += __shfl_xor_sync(0xffffffffu, yv[q].x, 8, 16);
                yv[q].y += __shfl_xor_sync(0xffffffffu, yv[q].y, 8, 16);
                yv[q].z += __shfl_xor_sync(0xffffffffu, yv[q].z, 8, 16);
                yv[q].w += __shfl_xor_sync(0xffffffffu, yv[q].w, 8, 16);
            }
            if ((tid & 12) == 0) {   // qs == 0: 4 writers per node (ch 0..3)
                int nl = tid >> 4;
#pragma unroll
                for (int q = 0; q < 4; q++) {
                    float4 o;
                    o.x = 0.25f * yv[q].x; o.y = 0.25f * yv[q].y;
                    o.z = 0.25f * yv[q].z; o.w = 0.25f * yv[q].w;
                    *(float4*)(g_pooled + (size_t)(node0 + nl) * 64 + c0 + q * 4) = o;
                }
            }
        }
    } else if (r6 == 0) {
        // ================= interaction branch: 128 rows x 64 cols =================
        float* sA = dsm;              // 128*68
        float* sW = dsm + 128 * 68;   // 64*68
        const int ib = q6;
        const int n0 = (ib & 1023) * 128;
        const int c0 = (ib >> 10) * 64;
        const int R = wp * 16;        // 8 warps x 16 rows

        float acc[8][4];
#pragma unroll
        for (int n = 0; n < 8; n++)
#pragma unroll
            for (int i = 0; i < 4; i++) acc[n][i] = 0.0f;

#pragma unroll 1
        for (int p = 0; p < 6; p++) {
            const float* Ea; const float* Eb;
            switch (p) {
                case 0: Ea = evx; Eb = evy; break;
                case 1: Ea = evx; Eb = exv; break;
                case 2: Ea = evx; Eb = eyv; break;
                case 3: Ea = evy; Eb = exv; break;
                case 4: Ea = evy; Eb = eyv; break;
                default: Ea = exv; Eb = eyv; break;
            }
            __syncthreads();
            for (int i4 = tid; i4 < 128 * 16; i4 += 256) {
                int r = i4 >> 4, k4 = i4 & 15;
                float4 x = ((const float4*)(Ea + (size_t)(n0 + r) * 64))[k4];
                float4 y = ((const float4*)(Eb + (size_t)(n0 + r) * 64))[k4];
                float4 v; v.x = x.x * y.x; v.y = x.y * y.y; v.z = x.z * y.z; v.w = x.w * y.w;
                *(float4*)(sA + r * 68 + k4 * 4) = tf32x4(v);
            }
            for (int i4 = tid; i4 < 64 * 16; i4 += 256) {
                int c = i4 >> 4, k4 = i4 & 15;
                *(float4*)(sW + c * 68 + k4 * 4) =
                    tf32x4(*(const float4*)(Wi1 + (size_t)(c0 + c) * 384 + p * 64 + k4 * 4));
            }
            __syncthreads();
            mma_stage16(sA, sW, acc, R, g, t);
        }
        __syncthreads();

        // epilogue: scatter, +bias, GELU -> g_h1
#pragma unroll
        for (int n = 0; n < 8; n++) {
            *(float2*)(sA + (R + g) * 68 + n * 8 + 2 * t) = make_float2(acc[n][0], acc[n][1]);
            *(float2*)(sA + (R + g + 8) * 68 + n * 8 + 2 * t) = make_float2(acc[n][2], acc[n][3]);
        }
        __syncthreads();
        {
            int r2 = tid >> 1, ch = tid & 1;   // 2 thr/row, 32 cols each
            int row = n0 + r2;
#pragma unroll
            for (int q = 0; q < 8; q++) {
                int c = ch * 32 + q * 4;
                float4 v = *(float4*)(sA + r2 * 68 + c);
                float4 bq = *(const float4*)(bi1 + c0 + c);
                float4 o;
                o.x = gelu_f(v.x + bq.x);
                o.y = gelu_f(v.y + bq.y);
                o.z = gelu_f(v.z + bq.z);
                o.w = gelu_f(v.w + bq.w);
                *(float4*)(g_h1 + (size_t)row * 128 + c0 + c) = o;
            }
        }
    } else {
        // ================= ci branch: 64 nodes -> g_cemb =================
        float* sA = dsm;                // 64*68
        float* sW = sA + 64 * 68;       // 64*68
        float* sCem = sW + 64 * 68;     // 64*68
        const int n0 = q6 * 64;
        const int rw = wp & 3, cw = wp >> 2;
        const int R = rw * 16;
        float acc[4][4];

        // S1: ci hidden = gelu(ci @ Wc1^T + bc1) -> sA (tf32); ci staged in sCem
        for (int i = tid; i < 640; i += 256) sW[i] = Wc1[i];
        if (tid < 64) sW[640 + tid] = bc1[tid];
        for (int i = tid; i < 640; i += 256) {
            int r = i / 10, k = i - r * 10;
            sCem[r * 12 + k] = cif[(size_t)(n0 + r) * 10 + k];
        }
        __syncthreads();
        for (int o = tid; o < 4096; o += 256) {
            int nl = o >> 6, c = o & 63;
            float a = sW[640 + c];
#pragma unroll
            for (int k = 0; k < 10; k++) a += sCem[nl * 12 + k] * sW[c * 10 + k];
            sA[nl * 68 + c] = to_tf32(gelu_f(a));
        }
        __syncthreads();

        // S2: cemb = LN(sA @ Wc2^T + bc2) -> sCem -> g_cemb
        for (int i4 = tid; i4 < 64 * 16; i4 += 256) {
            int c = i4 >> 4, k4 = i4 & 15;
            *(float4*)(sW + c * 68 + k4 * 4) =
                tf32x4(*(const float4*)(Wc2 + (size_t)c * 64 + k4 * 4));
        }
        __syncthreads();
#pragma unroll
        for (int n = 0; n < 4; n++)
#pragma unroll
            for (int i = 0; i < 4; i++) acc[n][i] = 0.0f;
        mma_stage8(sA, sW, acc, R, cw, g, t);
        scatter8(sCem, acc, bc2, R, cw, g, t);
        __syncthreads();
        ln64_256(sCem, gc, bnc, tid, 0);
        __syncthreads();
        for (int i4 = tid; i4 < 64 * 16; i4 += 256) {
            int r = i4 >> 4, k4 = i4 & 15;
            *(float4*)(g_cemb + (size_t)(n0 + r) * 64 + k4 * 4) =
                *(const float4*)(sCem + r * 68 + k4 * 4);
        }
    }
}

// =====================================================================
// k_tail: 64 nodes/block, 256 threads (8 warps), 3 CTAs/SM.
// load cemb -> Wi2+LN(iemb) -> merge+LN+GELU -> Wk1+GELU -> Wk2 -> out
// dyn smem: sA | sW | sIem | sCem, each 64x68  (69632 B)
// =====================================================================
__global__ void __launch_bounds__(256, 3)
k_tail(const float* __restrict__ Wi2, const float* __restrict__ bi2,
       const float* __restrict__ gi, const float* __restrict__ bni,
       const float* __restrict__ Wm, const float* __restrict__ bm,
       const float* __restrict__ gm, const float* __restrict__ bnm,
       const float* __restrict__ Wk1, const float* __restrict__ bk1,
       const float* __restrict__ Wk2, const float* __restrict__ bk2,
       float* __restrict__ out)
{
    float* sA = dsm;                // 64*68
    float* sW = sA + 64 * 68;       // 64*68
    float* sIem = sW + 64 * 68;     // 64*68
    float* sCem = sIem + 64 * 68;   // 64*68
    const int tid = threadIdx.x;
    const int lane = tid & 31, wp = tid >> 5;
    const int g = lane >> 2, t = lane & 3;
    const int n0 = blockIdx.x * 64;
    const int rw = wp & 3, cw = wp >> 2;
    const int R = rw * 16;
    float acc[4][4];

    // ---- load precomputed cemb (tf32-rounded) into sCem ----
    for (int i4 = tid; i4 < 64 * 16; i4 += 256) {
        int r = i4 >> 4, k4 = i4 & 15;
        *(float4*)(sCem + r * 68 + k4 * 4) =
            *(const float4*)(g_cemb + (size_t)(n0 + r) * 64 + k4 * 4);
    }

    // ---- S3: iemb = LN(h1 @ Wi2^T + bi2) -> sIem, K=128 in 2 chunks ----
#pragma unroll
    for (int n = 0; n < 4; n++)
#pragma unroll
        for (int i = 0; i < 4; i++) acc[n][i] = 0.0f;
#pragma unroll 1
    for (int kc = 0; kc < 128; kc += 64) {
        __syncthreads();
        for (int i4 = tid; i4 < 64 * 16; i4 += 256) {
            int r = i4 >> 4, k4 = i4 & 15;
            *(float4*)(sA + r * 68 + k4 * 4) =
                tf32x4(*(const float4*)(g_h1 + (size_t)(n0 + r) * 128 + kc + k4 * 4));
        }
        for (int i4 = tid; i4 < 64 * 16; i4 += 256) {
            int c = i4 >> 4, k4 = i4 & 15;
            *(float4*)(sW + c * 68 + k4 * 4) =
                tf32x4(*(const float4*)(Wi2 + (size_t)c * 128 + kc + k4 * 4));
        }
        __syncthreads();
        mma_stage8(sA, sW, acc, R, cw, g, t);
    }
    __syncthreads();
    scatter8(sIem, acc, bi2, R, cw, g, t);
    __syncthreads();
    ln64_256(sIem, gi, bni, tid, 0);
    __syncthreads();

    // ---- S4: merged = GELU(LN([pooled|iemb|cemb] @ Wm^T + bm)) -> sA ----
#pragma unroll
    for (int n = 0; n < 4; n++)
#pragma unroll
        for (int i = 0; i < 4; i++) acc[n][i] = 0.0f;
    // chunk0: pooled
    for (int i4 = tid; i4 < 64 * 16; i4 += 256) {
        int r = i4 >> 4, k4 = i4 & 15;
        *(float4*)(sA + r * 68 + k4 * 4) =
            tf32x4(*(const float4*)(g_pooled + (size_t)(n0 + r) * 64 + k4 * 4));
    }
    for (int i4 = tid; i4 < 64 * 16; i4 += 256) {
        int c = i4 >> 4, k4 = i4 & 15;
        *(float4*)(sW + c * 68 + k4 * 4) = tf32x4(*(const float4*)(Wm + (size_t)c * 192 + k4 * 4));
    }
    __syncthreads();
    mma_stage8(sA, sW, acc, R, cw, g, t);
    __syncthreads();
    // chunk1: iemb
    for (int i4 = tid; i4 < 64 * 16; i4 += 256) {
        int c = i4 >> 4, k4 = i4 & 15;
        *(float4*)(sW + c * 68 + k4 * 4) =
            tf32x4(*(const float4*)(Wm + (size_t)c * 192 + 64 + k4 * 4));
    }
    __syncthreads();
    mma_stage8(sIem, sW, acc, R, cw, g, t);
    __syncthreads();
    // chunk2: cemb
    for (int i4 = tid; i4 < 64 * 16; i4 += 256) {
        int c = i4 >> 4, k4 = i4 & 15;
        *(float4*)(sW + c * 68 + k4 * 4) =
            tf32x4(*(const float4*)(Wm + (size_t)c * 192 + 128 + k4 * 4));
    }
    __syncthreads();
    mma_stage8(sCem, sW, acc, R, cw, g, t);
    __syncthreads();     // all mma reads of sA done before overwrite
    scatter8(sA, acc, bm, R, cw, g, t);
    __syncthreads();
    ln64_256(sA, gm, bnm, tid, 1);
    __syncthreads();

    // ---- S5: hidden = GELU(merged @ Wk1^T + bk1) -> sCem (fp32) ----
    for (int i4 = tid; i4 < 64 * 16; i4 += 256) {
        int c = i4 >> 4, k4 = i4 & 15;
        *(float4*)(sW + c * 68 + k4 * 4) = tf32x4(*(const float4*)(Wk1 + (size_t)c * 64 + k4 * 4));
    }
    __syncthreads();
#pragma unroll
    for (int n = 0; n < 4; n++)
#pragma unroll
        for (int i = 0; i < 4; i++) acc[n][i] = 0.0f;
    mma_stage8(sA, sW, acc, R, cw, g, t);
#pragma unroll
    for (int n = 0; n < 4; n++) {
        int col = cw * 32 + n * 8 + 2 * t;
        float b0 = __ldg(bk1 + col);
        float b1 = __ldg(bk1 + col + 1);
        *(float2*)(sCem + (R + g) * 68 + col) =
            make_float2(gelu_f(acc[n][0] + b0), gelu_f(acc[n][1] + b1));
        *(float2*)(sCem + (R + g + 8) * 68 + col) =
            make_float2(gelu_f(acc[n][2] + b0), gelu_f(acc[n][3] + b1));
    }
    __syncthreads();

    // ---- S6: out = hidden @ Wk2^T + bk2 (scalar fp32) ----
    for (int i = tid; i < 512; i += 256) {
        int c = i >> 6, k = i & 63;
        sW[c * 68 + k] = Wk2[i];
    }
    if (tid < 8) sW[8 * 68 + tid] = bk2[tid];
    __syncthreads();
    for (int o = tid; o < 512; o += 256) {
        int nl = o >> 3, oc = o & 7;
        float a = sW[8 * 68 + oc];
#pragma unroll 8
        for (int k = 0; k < 64; k++) a += sCem[nl * 68 + k] * sW[oc * 68 + k];
        out[(size_t)(n0 + nl) * 8 + oc] = a;
    }
}

// =====================================================================
extern "C" void kernel_launch(void* const* d_in, const int* in_sizes, int n_in,
                              void* d_out, int out_size)
{
    const float* evx  = (const float*)d_in[0];
    const float* evy  = (const float*)d_in[1];
    const float* exv  = (const float*)d_in[2];
    const float* eyv  = (const float*)d_in[3];
    const float* cif  = (const float*)d_in[4];
    const float* W_in = (const float*)d_in[5];
    const float* b_in = (const float*)d_in[6];
    const float* W_out= (const float*)d_in[7];
    const float* b_out= (const float*)d_in[8];
    const float* g_at = (const float*)d_in[9];
    const float* b_at = (const float*)d_in[10];
    const float* Wi1  = (const float*)d_in[11];
    const float* bi1  = (const float*)d_in[12];
    const float* Wi2  = (const float*)d_in[13];
    const float* bi2  = (const float*)d_in[14];
    const float* gi   = (const float*)d_in[15];
    const float* bni  = (const float*)d_in[16];
    const float* Wc1  = (const float*)d_in[17];
    const float* bc1  = (const float*)d_in[18];
    const float* Wc2  = (const float*)d_in[19];
    const float* bc2  = (const float*)d_in[20];
    const float* gc   = (const float*)d_in[21];
    const float* bnc  = (const float*)d_in[22];
    const float* Wm   = (const float*)d_in[23];
    const float* bm   = (const float*)d_in[24];
    const float* gm   = (const float*)d_in[25];
    const float* bnm  = (const float*)d_in[26];
    const float* Wk1  = (const float*)d_in[27];
    const float* bk1  = (const float*)d_in[28];
    const float* Wk2  = (const float*)d_in[29];
    const float* bk2  = (const float*)d_in[30];
    float* out = (float*)d_out;

    const int FRONT_SMEM = (64 * 68 + 64 * 196) * 4;   // 67584
    const int TAIL_SMEM  = 4 * 64 * 68 * 4;            // 69632
    cudaFuncSetAttribute(k_front, cudaFuncAttributeMaxDynamicSharedMemorySize, FRONT_SMEM);
    cudaFuncSetAttribute(k_tail,  cudaFuncAttributeMaxDynamicSharedMemorySize, TAIL_SMEM);

    // 1) attention (8192) + interaction (2048) + ci (2048), interleaved
    k_front<<<12288, 256, FRONT_SMEM>>>(evx, evy, exv, eyv, W_in, b_in,
                                        W_out, b_out, g_at, b_at, Wi1, bi1,
                                        cif, Wc1, bc1, Wc2, bc2, gc, bnc);
    // 2) tail: iemb/merge/classifier
    k_tail<<<NN / 64, 256, TAIL_SMEM>>>(Wi2, bi2, gi, bni, Wm, bm, gm, bnm,
                                        Wk1, bk1, Wk2, bk2, out);

    (void)in_sizes; (void)n_in; (void)out_size;
}

// round 17
// speedup vs baseline: 1.0905x; 1.0905x over previous
#include <cuda_runtime.h>
#include <math.h>

#define NN 131072

// ---------------- scratch (static device arrays; no allocations) ----------------
__device__ __align__(16) float g_pooled[NN * 64];
__device__ __align__(16) float g_h1[NN * 128];
__device__ __align__(16) float g_cemb[NN * 64];

__device__ __forceinline__ float gelu_f(float x) {
    return 0.5f * x * (1.0f + erff(x * 0.70710678118654752f));
}
__device__ __forceinline__ float to_tf32(float x) {
    unsigned r;
    asm("cvt.rna.tf32.f32 %0, %1;" : "=r"(r) : "f"(x));
    return __uint_as_float(r);
}
__device__ __forceinline__ float4 tf32x4(float4 v) {
    v.x = to_tf32(v.x); v.y = to_tf32(v.y); v.z = to_tf32(v.z); v.w = to_tf32(v.w);
    return v;
}
__device__ __forceinline__ void mma8(float* c, const unsigned* a, const unsigned* b) {
    asm("mma.sync.aligned.m16n8k8.row.col.f32.tf32.tf32.f32 "
        "{%0,%1,%2,%3}, {%4,%5,%6,%7}, {%8,%9}, {%0,%1,%2,%3};"
        : "+f"(c[0]), "+f"(c[1]), "+f"(c[2]), "+f"(c[3])
        : "r"(a[0]), "r"(a[1]), "r"(a[2]), "r"(a[3]), "r"(b[0]), "r"(b[1]));
}

extern __shared__ float dsm[];

// ---- full-width mma over K=64: A rows R..R+15, W all 64 cols; strides sa/swd ----
__device__ __forceinline__ void mma16_str(const float* sA, int sa,
                                          const float* sW, int swd,
                                          float acc[8][4], int R, int g, int t) {
#pragma unroll
    for (int k8 = 0; k8 < 8; k8++) {
        int kb = k8 * 8;
        unsigned a[4], bb[8][2];
        a[0] = __float_as_uint(sA[(R + g) * sa + kb + t]);
        a[1] = __float_as_uint(sA[(R + g + 8) * sa + kb + t]);
        a[2] = __float_as_uint(sA[(R + g) * sa + kb + t + 4]);
        a[3] = __float_as_uint(sA[(R + g + 8) * sa + kb + t + 4]);
#pragma unroll
        for (int n = 0; n < 8; n++) {
            bb[n][0] = __float_as_uint(sW[(n * 8 + g) * swd + kb + t]);
            bb[n][1] = __float_as_uint(sW[(n * 8 + g) * swd + kb + t + 4]);
        }
#pragma unroll
        for (int n = 0; n < 8; n++) mma8(acc[n], a, bb[n]);
    }
}
// 8-warp split-col mma (tail): A rows R..R+15, W cols cw*32..+31
__device__ __forceinline__ void mma_stage8(const float* sA, const float* sW,
                                           float acc[4][4], int R, int cw, int g, int t) {
#pragma unroll
    for (int k8 = 0; k8 < 8; k8++) {
        int kb = k8 * 8;
        unsigned a[4], bb[4][2];
        a[0] = __float_as_uint(sA[(R + g) * 68 + kb + t]);
        a[1] = __float_as_uint(sA[(R + g + 8) * 68 + kb + t]);
        a[2] = __float_as_uint(sA[(R + g) * 68 + kb + t + 4]);
        a[3] = __float_as_uint(sA[(R + g + 8) * 68 + kb + t + 4]);
#pragma unroll
        for (int n = 0; n < 4; n++) {
            int cc = cw * 32 + n * 8 + g;
            bb[n][0] = __float_as_uint(sW[cc * 68 + kb + t]);
            bb[n][1] = __float_as_uint(sW[cc * 68 + kb + t + 4]);
        }
#pragma unroll
        for (int n = 0; n < 4; n++) mma8(acc[n], a, bb[n]);
    }
}
__device__ __forceinline__ void scatter8(float* dst, const float acc[4][4],
                                         const float* __restrict__ bias,
                                         int R, int cw, int g, int t) {
#pragma unroll
    for (int n = 0; n < 4; n++) {
        int col = cw * 32 + n * 8 + 2 * t;
        float b0 = __ldg(bias + col);
        float b1 = __ldg(bias + col + 1);
        *(float2*)(dst + (R + g) * 68 + col) = make_float2(acc[n][0] + b0, acc[n][1] + b1);
        *(float2*)(dst + (R + g + 8) * 68 + col) = make_float2(acc[n][2] + b0, acc[n][3] + b1);
    }
}
// LN over 64 rows (stride 68), 128 threads, 2 thr/row, tf32 store
__device__ __forceinline__ void ln64_128(float* buf, const float* __restrict__ gamma,
                                         const float* __restrict__ beta, int tid,
                                         int doGelu) {
    int r = tid >> 1, c0 = (tid & 1) * 32;
    float4 cv[8];
#pragma unroll
    for (int q = 0; q < 8; q++) cv[q] = *(float4*)(buf + r * 68 + c0 + q * 4);
    float s1 = 0.0f, s2 = 0.0f;
#pragma unroll
    for (int q = 0; q < 8; q++) {
        s1 += cv[q].x + cv[q].y + cv[q].z + cv[q].w;
        s2 += cv[q].x * cv[q].x + cv[q].y * cv[q].y + cv[q].z * cv[q].z + cv[q].w * cv[q].w;
    }
    s1 += __shfl_xor_sync(0xffffffffu, s1, 1, 2);
    s2 += __shfl_xor_sync(0xffffffffu, s2, 1, 2);
    float mean = s1 * (1.0f / 64.0f);
    float var = s2 * (1.0f / 64.0f) - mean * mean;
    float rstd = rsqrtf(var + 1e-5f);
#pragma unroll
    for (int q = 0; q < 8; q++) {
        int c = c0 + q * 4;
        float4 gq = *(const float4*)(gamma + c);
        float4 eq = *(const float4*)(beta + c);
        float4 o;
        o.x = (cv[q].x - mean) * rstd * gq.x + eq.x;
        o.y = (cv[q].y - mean) * rstd * gq.y + eq.y;
        o.z = (cv[q].z - mean) * rstd * gq.z + eq.z;
        o.w = (cv[q].w - mean) * rstd * gq.w + eq.w;
        if (doGelu) { o.x = gelu_f(o.x); o.y = gelu_f(o.y); o.z = gelu_f(o.z); o.w = gelu_f(o.w); }
        o = tf32x4(o);
        *(float4*)(buf + r * 68 + c) = o;
    }
}
// LN over 64 rows (stride 68), 256 threads, 4 thr/row, tf32 store
__device__ __forceinline__ void ln64_256(float* buf, const float* __restrict__ gamma,
                                         const float* __restrict__ beta, int tid,
                                         int doGelu) {
    int r = tid >> 2, c0 = (tid & 3) * 16;
    float4 cv[4];
#pragma unroll
    for (int q = 0; q < 4; q++) cv[q] = *(float4*)(buf + r * 68 + c0 + q * 4);
    float s1 = 0.0f, s2 = 0.0f;
#pragma unroll
    for (int q = 0; q < 4; q++) {
        s1 += cv[q].x + cv[q].y + cv[q].z + cv[q].w;
        s2 += cv[q].x * cv[q].x + cv[q].y * cv[q].y + cv[q].z * cv[q].z + cv[q].w * cv[q].w;
    }
    s1 += __shfl_xor_sync(0xffffffffu, s1, 1, 4);
    s1 += __shfl_xor_sync(0xffffffffu, s1, 2, 4);
    s2 += __shfl_xor_sync(0xffffffffu, s2, 1, 4);
    s2 += __shfl_xor_sync(0xffffffffu, s2, 2, 4);
    float mean = s1 * (1.0f / 64.0f);
    float var = s2 * (1.0f / 64.0f) - mean * mean;
    float rstd = rsqrtf(var + 1e-5f);
#pragma unroll
    for (int q = 0; q < 4; q++) {
        int c = c0 + q * 4;
        float4 gq = *(const float4*)(gamma + c);
        float4 eq = *(const float4*)(beta + c);
        float4 o;
        o.x = (cv[q].x - mean) * rstd * gq.x + eq.x;
        o.y = (cv[q].y - mean) * rstd * gq.y + eq.y;
        o.z = (cv[q].z - mean) * rstd * gq.z + eq.z;
        o.w = (cv[q].w - mean) * rstd * gq.w + eq.w;
        if (doGelu) { o.x = gelu_f(o.x); o.y = gelu_f(o.y); o.z = gelu_f(o.z); o.w = gelu_f(o.w); }
        o = tf32x4(o);
        *(float4*)(buf + r * 68 + c) = o;
    }
}

// =====================================================================
// k_front: 128 threads, 4 warps, 4 CTAs/SM (50176 B smem).
// 14336 blocks: bx%7: {1,3,5,6}->attention(8192), {0,4}->inter(4096), {2}->ci(2048)
// attention: sQKV 64x196 only — W staged into destination/dead columns.
// =====================================================================
__global__ void __launch_bounds__(128, 4)
k_front(const float* __restrict__ evx, const float* __restrict__ evy,
        const float* __restrict__ exv, const float* __restrict__ eyv,
        const float* __restrict__ Win, const float* __restrict__ bin,
        const float* __restrict__ Wout, const float* __restrict__ bout,
        const float* __restrict__ g_at, const float* __restrict__ b_at,
        const float* __restrict__ Wi1, const float* __restrict__ bi1,
        const float* __restrict__ cif,
        const float* __restrict__ Wc1, const float* __restrict__ bc1,
        const float* __restrict__ Wc2, const float* __restrict__ bc2,
        const float* __restrict__ gc, const float* __restrict__ bnc)
{
    const int bx = blockIdx.x;
    const int tid = threadIdx.x;
    const int lane = tid & 31, wp = tid >> 5;
    const int g = lane >> 2, t = lane & 3;
    const int r7 = bx % 7, q7 = bx / 7;

    if (r7 == 1 || r7 == 3 || r7 == 5 || r7 == 6) {
        // ================= attention: 16 nodes (64 rows) =================
        float* sQKV = dsm;              // 64*196
        const int aidx = (r7 == 1) ? 0 : (r7 == 3) ? 1 : (r7 == 5) ? 2 : 3;
        const int node0 = (q7 * 4 + aidx) * 16;
        const int R = wp * 16;

        // preload A fragments (tf32 edges) from gmem
        float af[8][4];
        {
            int r0 = R + g, r1 = R + g + 8;
            const float* base0 = ((r0 & 3) == 0) ? evx : ((r0 & 3) == 1) ? evy
                               : ((r0 & 3) == 2) ? exv : eyv;
            const float* base1 = ((r1 & 3) == 0) ? evx : ((r1 & 3) == 1) ? evy
                               : ((r1 & 3) == 2) ? exv : eyv;
            const float* p0 = base0 + (size_t)(node0 + (r0 >> 2)) * 64;
            const float* p1 = base1 + (size_t)(node0 + (r1 >> 2)) * 64;
#pragma unroll
            for (int k8 = 0; k8 < 8; k8++) {
                int kb = k8 * 8;
                af[k8][0] = to_tf32(__ldg(p0 + kb + t));
                af[k8][1] = to_tf32(__ldg(p1 + kb + t));
                af[k8][2] = to_tf32(__ldg(p0 + kb + t + 4));
                af[k8][3] = to_tf32(__ldg(p1 + kb + t + 4));
            }
        }

        // QKV: 3 chunks; W staged into the chunk's destination columns
#pragma unroll 1
        for (int wc = 0; wc < 3; wc++) {
            const int cbase = (wc < 2) ? wc * 64 : 128;
            __syncthreads();
            for (int i4 = tid; i4 < 64 * 16; i4 += 128) {
                int c = i4 >> 4, k4 = i4 & 15;
                *(float4*)(sQKV + c * 196 + cbase + k4 * 4) =
                    tf32x4(*(const float4*)(Win + (size_t)(wc * 64 + c) * 64 + k4 * 4));
            }
            __syncthreads();

            float acc[8][4];
#pragma unroll
            for (int n = 0; n < 8; n++)
#pragma unroll
                for (int i = 0; i < 4; i++) acc[n][i] = 0.0f;
#pragma unroll
            for (int k8 = 0; k8 < 8; k8++) {
                int kb = k8 * 8;
                unsigned bb[8][2];
#pragma unroll
                for (int n = 0; n < 8; n++) {
                    bb[n][0] = __float_as_uint(sQKV[(n * 8 + g) * 196 + cbase + kb + t]);
                    bb[n][1] = __float_as_uint(sQKV[(n * 8 + g) * 196 + cbase + kb + t + 4]);
                }
                const unsigned* a = (const unsigned*)af[k8];
#pragma unroll
                for (int n = 0; n < 8; n++) mma8(acc[n], a, bb[n]);
            }
            __syncthreads();   // all W reads done before overwriting with results
#pragma unroll
            for (int n = 0; n < 8; n++) {
                int col = n * 8 + 2 * t;
                float b0 = __ldg(bin + wc * 64 + col);
                float b1 = __ldg(bin + wc * 64 + col + 1);
                *(float2*)(sQKV + (R + g) * 196 + cbase + col) =
                    make_float2(acc[n][0] + b0, acc[n][1] + b1);
                *(float2*)(sQKV + (R + g + 8) * 196 + cbase + col) =
                    make_float2(acc[n][2] + b0, acc[n][3] + b1);
            }
        }
        __syncthreads();

        // attention: 128 threads, thread = (node nl, query qs, head-pair hp)
        {
            int nl = tid >> 3, qs = (tid >> 1) & 3, hp = tid & 1;
            float* qrow = sQKV + (nl * 4 + qs) * 196;
            float p[4][2];
#pragma unroll
            for (int ks = 0; ks < 4; ks++) {
                const float* krow = sQKV + (nl * 4 + ks) * 196 + 64;
#pragma unroll
                for (int hh = 0; hh < 2; hh++) {
                    int h = hp * 2 + hh;
                    float d = 0.0f;
#pragma unroll
                    for (int e4 = 0; e4 < 4; e4++) {
                        float4 qv = *(const float4*)(qrow + h * 16 + e4 * 4);
                        float4 kv = *(const float4*)(krow + h * 16 + e4 * 4);
                        d += qv.x * kv.x + qv.y * kv.y + qv.z * kv.z + qv.w * kv.w;
                    }
                    p[ks][hh] = d * 0.25f;
                }
            }
#pragma unroll
            for (int hh = 0; hh < 2; hh++) {
                float m = fmaxf(fmaxf(p[0][hh], p[1][hh]), fmaxf(p[2][hh], p[3][hh]));
                float s = 0.0f;
#pragma unroll
                for (int ks = 0; ks < 4; ks++) { p[ks][hh] = expf(p[ks][hh] - m); s += p[ks][hh]; }
                float inv = 1.0f / s;
#pragma unroll
                for (int ks = 0; ks < 4; ks++) p[ks][hh] *= inv;
            }
#pragma unroll
            for (int e = 0; e < 8; e++) {
                int e4 = hp * 8 + e;
                int hh = e >> 2;
                float4 o = {0.0f, 0.0f, 0.0f, 0.0f};
#pragma unroll
                for (int ks = 0; ks < 4; ks++) {
                    float4 v = *(const float4*)(sQKV + (nl * 4 + ks) * 196 + 128 + e4 * 4);
                    float pk = p[ks][hh];
                    o.x += pk * v.x; o.y += pk * v.y; o.z += pk * v.z; o.w += pk * v.w;
                }
                *(float4*)(qrow + e4 * 4) = o;
            }
        }
        __syncthreads();

        // out-proj: stage Wout into dead V region (cols 128..191)
        for (int i4 = tid; i4 < 64 * 16; i4 += 128) {
            int c = i4 >> 4, k4 = i4 & 15;
            *(float4*)(sQKV + c * 196 + 128 + k4 * 4) =
                tf32x4(*(const float4*)(Wout + (size_t)c * 64 + k4 * 4));
        }
        __syncthreads();
        {
            float acc[8][4];
#pragma unroll
            for (int n = 0; n < 8; n++)
#pragma unroll
                for (int i = 0; i < 4; i++) acc[n][i] = 0.0f;
#pragma unroll
            for (int k8 = 0; k8 < 8; k8++) {
                int kb = k8 * 8;
                unsigned a[4], bb[8][2];
                a[0] = __float_as_uint(to_tf32(sQKV[(R + g) * 196 + kb + t]));
                a[1] = __float_as_uint(to_tf32(sQKV[(R + g + 8) * 196 + kb + t]));
                a[2] = __float_as_uint(to_tf32(sQKV[(R + g) * 196 + kb + t + 4]));
                a[3] = __float_as_uint(to_tf32(sQKV[(R + g + 8) * 196 + kb + t + 4]));
#pragma unroll
                for (int n = 0; n < 8; n++) {
                    bb[n][0] = __float_as_uint(sQKV[(n * 8 + g) * 196 + 128 + kb + t]);
                    bb[n][1] = __float_as_uint(sQKV[(n * 8 + g) * 196 + 128 + kb + t + 4]);
                }
#pragma unroll
                for (int n = 0; n < 8; n++) mma8(acc[n], a, bb[n]);
            }
            // scatter into K region (cols 64..127), own warp rows — no W overlap
#pragma unroll
            for (int n = 0; n < 8; n++) {
                int col = n * 8 + 2 * t;
                *(float2*)(sQKV + (R + g) * 196 + 64 + col) = make_float2(acc[n][0], acc[n][1]);
                *(float2*)(sQKV + (R + g + 8) * 196 + 64 + col) = make_float2(acc[n][2], acc[n][3]);
            }
        }
        __syncthreads();

        // epilogue: +bout +edge residual -> LN -> butterfly pooled mean (registers)
        {
            int r = tid >> 1, ch = tid & 1;
            int c0 = ch * 32;
            int node = node0 + (r >> 2), s = r & 3;
            const float* ebase = ((s == 0) ? evx : (s == 1) ? evy : (s == 2) ? exv : eyv)
                                 + (size_t)node * 64;
            float4 cv[8];
#pragma unroll
            for (int q = 0; q < 8; q++) {
                int c = c0 + q * 4;
                float4 v = *(float4*)(sQKV + r * 196 + 64 + c);
                float4 e = *(const float4*)(ebase + c);
                float4 bq = *(const float4*)(bout + c);
                v.x += bq.x + e.x; v.y += bq.y + e.y;
                v.z += bq.z + e.z; v.w += bq.w + e.w;
                cv[q] = v;
            }
            float s1 = 0.0f, s2 = 0.0f;
#pragma unroll
            for (int q = 0; q < 8; q++) {
                s1 += cv[q].x + cv[q].y + cv[q].z + cv[q].w;
                s2 += cv[q].x * cv[q].x + cv[q].y * cv[q].y + cv[q].z * cv[q].z + cv[q].w * cv[q].w;
            }
            s1 += __shfl_xor_sync(0xffffffffu, s1, 1, 2);
            s2 += __shfl_xor_sync(0xffffffffu, s2, 1, 2);
            float mean = s1 * (1.0f / 64.0f);
            float var = s2 * (1.0f / 64.0f) - mean * mean;
            float rstd = rsqrtf(var + 1e-5f);
            float4 yv[8];
#pragma unroll
            for (int q = 0; q < 8; q++) {
                int c = c0 + q * 4;
                float4 gq = *(const float4*)(g_at + c);
                float4 eq = *(const float4*)(b_at + c);
                yv[q].x = (cv[q].x - mean) * rstd * gq.x + eq.x;
                yv[q].y = (cv[q].y - mean) * rstd * gq.y + eq.y;
                yv[q].z = (cv[q].z - mean) * rstd * gq.z + eq.z;
                yv[q].w = (cv[q].w - mean) * rstd * gq.w + eq.w;
            }
#pragma unroll
            for (int q = 0; q < 8; q++) {
                yv[q].x += __shfl_xor_sync(0xffffffffu, yv[q].x, 2, 8);
                yv[q].y += __shfl_xor_sync(0xffffffffu, yv[q].y, 2, 8);
                yv[q].z += __shfl_xor_sync(0xffffffffu, yv[q].z, 2, 8);
                yv[q].w += __shfl_xor_sync(0xffffffffu, yv[q].w, 2, 8);
                yv[q].x += __shfl_xor_sync(0xffffffffu, yv[q].x, 4, 8);
                yv[q].y += __shfl_xor_sync(0xffffffffu, yv[q].y, 4, 8);
                yv[q].z += __shfl_xor_sync(0xffffffffu, yv[q].z, 4, 8);
                yv[q].w += __shfl_xor_sync(0xffffffffu, yv[q].w, 4, 8);
            }
            if ((tid & 6) == 0) {
                int nl = tid >> 3;
#pragma unroll
                for (int q = 0; q < 8; q++) {
                    float4 o;
                    o.x = 0.25f * yv[q].x; o.y = 0.25f * yv[q].y;
                    o.z = 0.25f * yv[q].z; o.w = 0.25f * yv[q].w;
                    *(float4*)(g_pooled + (size_t)(node0 + nl) * 64 + c0 + q * 4) = o;
                }
            }
        }
    } else if (r7 != 2) {
        // ================= interaction: 64 rows x 64 cols =================
        float* sA = dsm;              // 64*68
        float* sW = dsm + 64 * 68;    // 64*68
        const int ib = q7 * 2 + (r7 == 4 ? 1 : 0);
        const int n0 = (ib & 2047) * 64;
        const int c0 = (ib >> 11) * 64;
        const int R = wp * 16;

        float acc[8][4];
#pragma unroll
        for (int n = 0; n < 8; n++)
#pragma unroll
            for (int i = 0; i < 4; i++) acc[n][i] = 0.0f;

#pragma unroll 1
        for (int p = 0; p < 6; p++) {
            const float* Ea; const float* Eb;
            switch (p) {
                case 0: Ea = evx; Eb = evy; break;
                case 1: Ea = evx; Eb = exv; break;
                case 2: Ea = evx; Eb = eyv; break;
                case 3: Ea = evy; Eb = exv; break;
                case 4: Ea = evy; Eb = eyv; break;
                default: Ea = exv; Eb = eyv; break;
            }
            __syncthreads();
            for (int i4 = tid; i4 < 64 * 16; i4 += 128) {
                int r = i4 >> 4, k4 = i4 & 15;
                float4 x = ((const float4*)(Ea + (size_t)(n0 + r) * 64))[k4];
                float4 y = ((const float4*)(Eb + (size_t)(n0 + r) * 64))[k4];
                float4 v; v.x = x.x * y.x; v.y = x.y * y.y; v.z = x.z * y.z; v.w = x.w * y.w;
                *(float4*)(sA + r * 68 + k4 * 4) = tf32x4(v);
            }
            for (int i4 = tid; i4 < 64 * 16; i4 += 128) {
                int c = i4 >> 4, k4 = i4 & 15;
                *(float4*)(sW + c * 68 + k4 * 4) =
                    tf32x4(*(const float4*)(Wi1 + (size_t)(c0 + c) * 384 + p * 64 + k4 * 4));
            }
            __syncthreads();
            mma16_str(sA, 68, sW, 68, acc, R, g, t);
        }
        __syncthreads();
        // scatter +bias, GELU -> g_h1
#pragma unroll
        for (int n = 0; n < 8; n++) {
            *(float2*)(sA + (R + g) * 68 + n * 8 + 2 * t) = make_float2(acc[n][0], acc[n][1]);
            *(float2*)(sA + (R + g + 8) * 68 + n * 8 + 2 * t) = make_float2(acc[n][2], acc[n][3]);
        }
        __syncthreads();
        {
            int r2 = tid >> 1, ch = tid & 1;
            int row = n0 + r2;
#pragma unroll
            for (int q = 0; q < 8; q++) {
                int c = ch * 32 + q * 4;
                float4 v = *(float4*)(sA + r2 * 68 + c);
                float4 bq = *(const float4*)(bi1 + c0 + c);
                float4 o;
                o.x = gelu_f(v.x + bq.x);
                o.y = gelu_f(v.y + bq.y);
                o.z = gelu_f(v.z + bq.z);
                o.w = gelu_f(v.w + bq.w);
                *(float4*)(g_h1 + (size_t)row * 128 + c0 + c) = o;
            }
        }
    } else {
        // ================= ci branch: 64 nodes -> g_cemb =================
        float* sA = dsm;              // 64*68
        float* sW = dsm + 64 * 68;    // 64*68 (+ci staging at offset 704)
        const int n0 = q7 * 64;
        const int R = wp * 16;
        float acc[8][4];

        // S1: ci hidden = gelu(ci @ Wc1^T + bc1) -> sA (tf32)
        for (int i = tid; i < 640; i += 128) sW[i] = Wc1[i];
        if (tid < 64) sW[640 + tid] = bc1[tid];
        for (int i = tid; i < 640; i += 128) {
            int r = i / 10, k = i - r * 10;
            sW[704 + r * 12 + k] = cif[(size_t)(n0 + r) * 10 + k];
        }
        __syncthreads();
        for (int o = tid; o < 4096; o += 128) {
            int nl = o >> 6, c = o & 63;
            float a = sW[640 + c];
#pragma unroll
            for (int k = 0; k < 10; k++) a += sW[704 + nl * 12 + k] * sW[c * 10 + k];
            sA[nl * 68 + c] = to_tf32(gelu_f(a));
        }
        __syncthreads();

        // S2: cemb = LN(sA @ Wc2^T + bc2) in place -> g_cemb
        for (int i4 = tid; i4 < 64 * 16; i4 += 128) {
            int c = i4 >> 4, k4 = i4 & 15;
            *(float4*)(sW + c * 68 + k4 * 4) =
                tf32x4(*(const float4*)(Wc2 + (size_t)c * 64 + k4 * 4));
        }
        __syncthreads();
#pragma unroll
        for (int n = 0; n < 8; n++)
#pragma unroll
            for (int i = 0; i < 4; i++) acc[n][i] = 0.0f;
        mma16_str(sA, 68, sW, 68, acc, R, g, t);
        // scatter (+bias) into sA itself: own-warp rows, own reads complete
#pragma unroll
        for (int n = 0; n < 8; n++) {
            int col = n * 8 + 2 * t;
            float b0 = __ldg(bc2 + col);
            float b1 = __ldg(bc2 + col + 1);
            *(float2*)(sA + (R + g) * 68 + col) = make_float2(acc[n][0] + b0, acc[n][1] + b1);
            *(float2*)(sA + (R + g + 8) * 68 + col) = make_float2(acc[n][2] + b0, acc[n][3] + b1);
        }
        __syncthreads();
        ln64_128(sA, gc, bnc, tid, 0);
        __syncthreads();
        for (int i4 = tid; i4 < 64 * 16; i4 += 128) {
            int r = i4 >> 4, k4 = i4 & 15;
            *(float4*)(g_cemb + (size_t)(n0 + r) * 64 + k4 * 4) =
                *(const float4*)(sA + r * 68 + k4 * 4);
        }
    }
}

// =====================================================================
// k_tail: 64 nodes/block, 256 threads (8 warps), 3 CTAs/SM. (R16-proven, 156us)
// =====================================================================
__global__ void __launch_bounds__(256, 3)
k_tail(const float* __restrict__ Wi2, const float* __restrict__ bi2,
       const float* __restrict__ gi, const float* __restrict__ bni,
       const float* __restrict__ Wm, const float* __restrict__ bm,
       const float* __restrict__ gm, const float* __restrict__ bnm,
       const float* __restrict__ Wk1, const float* __restrict__ bk1,
       const float* __restrict__ Wk2, const float* __restrict__ bk2,
       float* __restrict__ out)
{
    float* sA = dsm;
    float* sW = sA + 64 * 68;
    float* sIem = sW + 64 * 68;
    float* sCem = sIem + 64 * 68;
    const int tid = threadIdx.x;
    const int lane = tid & 31, wp = tid >> 5;
    const int g = lane >> 2, t = lane & 3;
    const int n0 = blockIdx.x * 64;
    const int rw = wp & 3, cw = wp >> 2;
    const int R = rw * 16;
    float acc[4][4];

    for (int i4 = tid; i4 < 64 * 16; i4 += 256) {
        int r = i4 >> 4, k4 = i4 & 15;
        *(float4*)(sCem + r * 68 + k4 * 4) =
            *(const float4*)(g_cemb + (size_t)(n0 + r) * 64 + k4 * 4);
    }

    // S3: iemb = LN(h1 @ Wi2^T + bi2) -> sIem, K=128 in 2 chunks
#pragma unroll
    for (int n = 0; n < 4; n++)
#pragma unroll
        for (int i = 0; i < 4; i++) acc[n][i] = 0.0f;
#pragma unroll 1
    for (int kc = 0; kc < 128; kc += 64) {
        __syncthreads();
        for (int i4 = tid; i4 < 64 * 16; i4 += 256) {
            int r = i4 >> 4, k4 = i4 & 15;
            *(float4*)(sA + r * 68 + k4 * 4) =
                tf32x4(*(const float4*)(g_h1 + (size_t)(n0 + r) * 128 + kc + k4 * 4));
        }
        for (int i4 = tid; i4 < 64 * 16; i4 += 256) {
            int c = i4 >> 4, k4 = i4 & 15;
            *(float4*)(sW + c * 68 + k4 * 4) =
                tf32x4(*(const float4*)(Wi2 + (size_t)c * 128 + kc + k4 * 4));
        }
        __syncthreads();
        mma_stage8(sA, sW, acc, R, cw, g, t);
    }
    __syncthreads();
    scatter8(sIem, acc, bi2, R, cw, g, t);
    __syncthreads();
    ln64_256(sIem, gi, bni, tid, 0);
    __syncthreads();

    // S4: merged = GELU(LN([pooled|iemb|cemb] @ Wm^T + bm)) -> sA
#pragma unroll
    for (int n = 0; n < 4; n++)
#pragma unroll
        for (int i = 0; i < 4; i++) acc[n][i] = 0.0f;
    for (int i4 = tid; i4 < 64 * 16; i4 += 256) {
        int r = i4 >> 4, k4 = i4 & 15;
        *(float4*)(sA + r * 68 + k4 * 4) =
            tf32x4(*(const float4*)(g_pooled + (size_t)(n0 + r) * 64 + k4 * 4));
    }
    for (int i4 = tid; i4 < 64 * 16; i4 += 256) {
        int c = i4 >> 4, k4 = i4 & 15;
        *(float4*)(sW + c * 68 + k4 * 4) = tf32x4(*(const float4*)(Wm + (size_t)c * 192 + k4 * 4));
    }
    __syncthreads();
    mma_stage8(sA, sW, acc, R, cw, g, t);
    __syncthreads();
    for (int i4 = tid; i4 < 64 * 16; i4 += 256) {
        int c = i4 >> 4, k4 = i4 & 15;
        *(float4*)(sW + c * 68 + k4 * 4) =
            tf32x4(*(const float4*)(Wm + (size_t)c * 192 + 64 + k4 * 4));
    }
    __syncthreads();
    mma_stage8(sIem, sW, acc, R, cw, g, t);
    __syncthreads();
    for (int i4 = tid; i4 < 64 * 16; i4 += 256) {
        int c = i4 >> 4, k4 = i4 & 15;
        *(float4*)(sW + c * 68 + k4 * 4) =
            tf32x4(*(const float4*)(Wm + (size_t)c * 192 + 128 + k4 * 4));
    }
    __syncthreads();
    mma_stage8(sCem, sW, acc, R, cw, g, t);
    __syncthreads();
    scatter8(sA, acc, bm, R, cw, g, t);
    __syncthreads();
    ln64_256(sA, gm, bnm, tid, 1);
    __syncthreads();

    // S5: hidden = GELU(merged @ Wk1^T + bk1) -> sCem (fp32)
    for (int i4 = tid; i4 < 64 * 16; i4 += 256) {
        int c = i4 >> 4, k4 = i4 & 15;
        *(float4*)(sW + c * 68 + k4 * 4) = tf32x4(*(const float4*)(Wk1 + (size_t)c * 64 + k4 * 4));
    }
    __syncthreads();
#pragma unroll
    for (int n = 0; n < 4; n++)
#pragma unroll
        for (int i = 0; i < 4; i++) acc[n][i] = 0.0f;
    mma_stage8(sA, sW, acc, R, cw, g, t);
#pragma unroll
    for (int n = 0; n < 4; n++) {
        int col = cw * 32 + n * 8 + 2 * t;
        float b0 = __ldg(bk1 + col);
        float b1 = __ldg(bk1 + col + 1);
        *(float2*)(sCem + (R + g) * 68 + col) =
            make_float2(gelu_f(acc[n][0] + b0), gelu_f(acc[n][1] + b1));
        *(float2*)(sCem + (R + g + 8) * 68 + col) =
            make_float2(gelu_f(acc[n][2] + b0), gelu_f(acc[n][3] + b1));
    }
    __syncthreads();

    // S6: out = hidden @ Wk2^T + bk2 (scalar fp32)
    for (int i = tid; i < 512; i += 256) {
        int c = i >> 6, k = i & 63;
        sW[c * 68 + k] = Wk2[i];
    }
    if (tid < 8) sW[8 * 68 + tid] = bk2[tid];
    __syncthreads();
    for (int o = tid; o < 512; o += 256) {
        int nl = o >> 3, oc = o & 7;
        float a = sW[8 * 68 + oc];
#pragma unroll 8
        for (int k = 0; k < 64; k++) a += sCem[nl * 68 + k] * sW[oc * 68 + k];
        out[(size_t)(n0 + nl) * 8 + oc] = a;
    }
}

// =====================================================================
extern "C" void kernel_launch(void* const* d_in, const int* in_sizes, int n_in,
                              void* d_out, int out_size)
{
    const float* evx  = (const float*)d_in[0];
    const float* evy  = (const float*)d_in[1];
    const float* exv  = (const float*)d_in[2];
    const float* eyv  = (const float*)d_in[3];
    const float* cif  = (const float*)d_in[4];
    const float* W_in = (const float*)d_in[5];
    const float* b_in = (const float*)d_in[6];
    const float* W_out= (const float*)d_in[7];
    const float* b_out= (const float*)d_in[8];
    const float* g_at = (const float*)d_in[9];
    const float* b_at = (const float*)d_in[10];
    const float* Wi1  = (const float*)d_in[11];
    const float* bi1  = (const float*)d_in[12];
    const float* Wi2  = (const float*)d_in[13];
    const float* bi2  = (const float*)d_in[14];
    const float* gi   = (const float*)d_in[15];
    const float* bni  = (const float*)d_in[16];
    const float* Wc1  = (const float*)d_in[17];
    const float* bc1  = (const float*)d_in[18];
    const float* Wc2  = (const float*)d_in[19];
    const float* bc2  = (const float*)d_in[20];
    const float* gc   = (const float*)d_in[21];
    const float* bnc  = (const float*)d_in[22];
    const float* Wm   = (const float*)d_in[23];
    const float* bm   = (const float*)d_in[24];
    const float* gm   = (const float*)d_in[25];
    const float* bnm  = (const float*)d_in[26];
    const float* Wk1  = (const float*)d_in[27];
    const float* bk1  = (const float*)d_in[28];
    const float* Wk2  = (const float*)d_in[29];
    const float* bk2  = (const float*)d_in[30];
    float* out = (float*)d_out;

    const int FRONT_SMEM = 64 * 196 * 4;     // 50176
    const int TAIL_SMEM  = 4 * 64 * 68 * 4;  // 69632
    cudaFuncSetAttribute(k_front, cudaFuncAttributeMaxDynamicSharedMemorySize, FRONT_SMEM);
    cudaFuncSetAttribute(k_tail,  cudaFuncAttributeMaxDynamicSharedMemorySize, TAIL_SMEM);

    // attention 8192 + inter 4096 + ci 2048, interleaved 4:2:1 via %7
    k_front<<<14336, 128, FRONT_SMEM>>>(evx, evy, exv, eyv, W_in, b_in,
                                        W_out, b_out, g_at, b_at, Wi1, bi1,
                                        cif, Wc1, bc1, Wc2, bc2, gc, bnc);
    k_tail<<<NN / 64, 256, TAIL_SMEM>>>(Wi2, bi2, gi, bni, Wm, bm, gm, bnm,
                                        Wk1, bk1, Wk2, bk2, out);

    (void)in_sizes; (void)n_in; (void)out_size;
}